// round 13
// baseline (speedup 1.0000x reference)
#include <cuda_runtime.h>
#include <cuda_bf16.h>
#include <cstdint>

// Problem dims
#define ND_  128   // docs
#define LD_  128   // doc tokens (t)  -> GEMM M
#define E_   128   // embed          -> GEMM K
#define NQ_  128   // queries
#define LQ_  32    // query tokens (l)-> GEMM N

#define QG_PER_CTA 8    // queries per CTA (one per warp)
#define DG_STRIDE  18   // persistent stride over the 64 doc-pair groups

// padded smem rows: 128 bf16 + 8 pad = 272 bytes (conflict-free ldmatrix)
#define ROW_B   272
#define QT_B    (32 * ROW_B)      // 8704 B per query tile
#define DT_B    (128 * ROW_B)     // 34816 B per doc tile
#define SMEM_TOTAL (2 * DT_B)     // 69632 B; query staging (8*QT_B) aliases this space

// bf16 scratch (module-scope device globals: no runtime allocation)
static __device__ __nv_bfloat16 g_doc[ND_ * LD_ * E_];   // [d][t][e]
static __device__ __nv_bfloat16 g_qT [NQ_ * LQ_ * E_];   // [q][l][e]

// ---------------- fused convert kernel ----------------
#define CVT_DOC_BLOCKS 512

__global__ void __launch_bounds__(256)
cvt_fused_kernel(const float* __restrict__ doc, const float* __restrict__ query) {
    __shared__ float s[128 * 33];   // query branch only
    if (blockIdx.x < CVT_DOC_BLOCKS) {
        int b0 = blockIdx.x * 1024 + threadIdx.x;
        float4 v[4];
        #pragma unroll
        for (int u = 0; u < 4; u++)
            v[u] = reinterpret_cast<const float4*>(doc)[b0 + u * 256];
        #pragma unroll
        for (int u = 0; u < 4; u++) {
            __nv_bfloat162 lo = __floats2bfloat162_rn(v[u].x, v[u].y);
            __nv_bfloat162 hi = __floats2bfloat162_rn(v[u].z, v[u].w);
            uint2 pk;
            pk.x = *reinterpret_cast<uint32_t*>(&lo);
            pk.y = *reinterpret_cast<uint32_t*>(&hi);
            reinterpret_cast<uint2*>(g_doc)[b0 + u * 256] = pk;
        }
    } else {
        int q   = blockIdx.x - CVT_DOC_BLOCKS;   // 0..127
        int tid = threadIdx.x;
        const float* p = query + q * 4096;
        #pragma unroll
        for (int j = 0; j < 16; j++) {
            int idx = tid + j * 256;               // idx = e*32 + l
            s[(idx >> 5) * 33 + (idx & 31)] = p[idx];
        }
        __syncthreads();
        #pragma unroll
        for (int j = 0; j < 16; j++) {
            int idx = tid + j * 256;               // idx = l*128 + e
            int l = idx >> 7, e = idx & 127;
            g_qT[q * 4096 + idx] = __float2bfloat16(s[e * 33 + l]);
        }
    }
}

// ---------------- PTX helpers ----------------

__device__ __forceinline__ uint32_t s2u(const void* p) {
    uint32_t a;
    asm("{ .reg .u64 t; cvta.to.shared.u64 t, %1; cvt.u32.u64 %0, t; }"
        : "=r"(a) : "l"(p));
    return a;
}

__device__ __forceinline__ void ldsm_x4(uint32_t& r0, uint32_t& r1,
                                        uint32_t& r2, uint32_t& r3, uint32_t addr) {
    asm volatile("ldmatrix.sync.aligned.m8n8.x4.shared.b16 {%0,%1,%2,%3}, [%4];"
                 : "=r"(r0), "=r"(r1), "=r"(r2), "=r"(r3) : "r"(addr));
}

__device__ __forceinline__ void mma16816(float* c, uint32_t a0, uint32_t a1,
                                         uint32_t a2, uint32_t a3,
                                         uint32_t b0, uint32_t b1) {
    asm volatile(
        "mma.sync.aligned.m16n8k16.row.col.f32.bf16.bf16.f32 "
        "{%0,%1,%2,%3}, {%4,%5,%6,%7}, {%8,%9}, {%0,%1,%2,%3};"
        : "+f"(c[0]), "+f"(c[1]), "+f"(c[2]), "+f"(c[3])
        : "r"(a0), "r"(a1), "r"(a2), "r"(a3), "r"(b0), "r"(b1));
}

__device__ __forceinline__ void cp_async16(uint32_t saddr, const void* gaddr) {
    asm volatile("cp.async.cg.shared.global [%0], [%1], 16;"
                 :: "r"(saddr), "l"(gaddr) : "memory");
}
__device__ __forceinline__ void cp_commit() {
    asm volatile("cp.async.commit_group;" ::: "memory");
}

// ---------------- main kernel ----------------
// Persistent single-wave grid: (16 qgroups, 18) = 288 CTAs, 2 CTAs/SM.
// CTA (x,y): queries fixed (qg = x, one per warp); docs d = 2g, 2g+1 for
// g = y, y+18, y+36, y+54 (<64)  ->  6 or 8 docs per CTA, one prologue.

__global__ void __launch_bounds__(256, 2)
colbert_maxsim_kernel(float* __restrict__ out) {
    extern __shared__ char smem[];
    const uint32_t sb   = s2u(smem);
    const int tid  = threadIdx.x;
    const int wid  = tid >> 5;
    const int lane = tid & 31;
    const int qg   = blockIdx.x;   // 0..15
    const int dgy  = blockIdx.y;   // 0..17
    const int mi   = lane >> 3;    // ldmatrix 8-lane group 0..3

    // ---- 1) stage 8 query tiles into smem (region later reused as doc buffers) ----
    {
        const __nv_bfloat16* Q = g_qT + (size_t)qg * (QG_PER_CTA * LQ_ * E_);
        #pragma unroll
        for (int j = 0; j < 16; j++) {
            int c    = tid + j * 256;          // 4096 uint4 chunks total
            int tile = c >> 9;                 // 512 chunks per tile
            int rc   = c & 511;
            int row  = rc >> 4;                // 16 chunks per 128-bf16 row
            int col  = rc & 15;
            uint4 v = reinterpret_cast<const uint4*>(Q + tile * 4096 + row * 128)[col];
            *reinterpret_cast<uint4*>(smem + tile * QT_B + row * ROW_B + col * 16) = v;
        }
    }
    __syncthreads();

    // ---- 2) load this warp's entire B tile (32 l x 128 e) into 64 registers ----
    uint32_t breg[8][4][2];
    {
        const uint32_t qb = sb + wid * QT_B;
        #pragma unroll
        for (int k = 0; k < 8; k++) {
            #pragma unroll
            for (int p = 0; p < 2; p++) {
                uint32_t addr = qb + (uint32_t)((p * 16 + (mi >> 1) * 8 + (lane & 7)) * ROW_B
                                                + (k * 16 + (mi & 1) * 8) * 2);
                ldsm_x4(breg[k][2 * p][0], breg[k][2 * p][1],
                        breg[k][2 * p + 1][0], breg[k][2 * p + 1][1], addr);
            }
        }
    }
    __syncthreads();   // all warps done reading query smem; region is now free

    // ---- 3) persistent doc loop (cp.async double buffer aliased over query region) ----
    const uint32_t dbuf[2] = { sb, sb + DT_B };
    // number of doc-pair groups for this y: g = dgy, dgy+18, ... < 64
    const int ndocs = 2 * ((64 - dgy + DG_STRIDE - 1) / DG_STRIDE);   // 6 or 8
    int d = 2 * dgy;

    // prefetch first doc tile
    {
        const __nv_bfloat16* A = g_doc + (size_t)d * (LD_ * E_);
        #pragma unroll
        for (int j = 0; j < 8; j++) {
            int c = tid + j * 256;             // 2048 chunks
            int row = c >> 4, col = c & 15;
            cp_async16(dbuf[0] + row * ROW_B + col * 16, A + row * 128 + col * 8);
        }
        cp_commit();
    }

    // per-lane constant part of the A ldmatrix address
    const uint32_t a_lane_off = (uint32_t)(((mi & 1) * 8 + (lane & 7)) * ROW_B
                                           + ((mi >> 1) * 8) * 2);
    const int q = qg * QG_PER_CTA + wid;

    #pragma unroll 1
    for (int it = 0; it < ndocs; it++) {
        // next doc in this CTA's sequence: within pair -> d+1; pair->next group
        const int nd = (d & 1) ? (d + 2 * DG_STRIDE - 1) : (d + 1);

        if (it < ndocs - 1) {
            const __nv_bfloat16* A = g_doc + (size_t)nd * (LD_ * E_);
            const uint32_t dst = dbuf[(it + 1) & 1];
            #pragma unroll
            for (int j = 0; j < 8; j++) {
                int c = tid + j * 256;
                int row = c >> 4, col = c & 15;
                cp_async16(dst + row * ROW_B + col * 16, A + row * 128 + col * 8);
            }
            cp_commit();
            asm volatile("cp.async.wait_group 1;" ::: "memory");
        } else {
            asm volatile("cp.async.wait_group 0;" ::: "memory");
        }
        __syncthreads();

        const uint32_t ab = dbuf[it & 1] + a_lane_off;

        float cmax[4][2];
        #pragma unroll
        for (int nt = 0; nt < 4; nt++) { cmax[nt][0] = -1e30f; cmax[nt][1] = -1e30f; }

        #pragma unroll 1
        for (int mt = 0; mt < 8; mt++) {
            float acc[4][4];
            #pragma unroll
            for (int nt = 0; nt < 4; nt++)
                #pragma unroll
                for (int r = 0; r < 4; r++) acc[nt][r] = 0.0f;

            #pragma unroll
            for (int k = 0; k < 8; k++) {
                uint32_t a0, a1, a2, a3;
                ldsm_x4(a0, a1, a2, a3, ab + (uint32_t)(mt * 16 * ROW_B + k * 32));
                #pragma unroll
                for (int nt = 0; nt < 4; nt++)
                    mma16816(acc[nt], a0, a1, a2, a3, breg[k][nt][0], breg[k][nt][1]);
            }
            // running column-max over t (rows m and m+8 of this M-tile)
            #pragma unroll
            for (int nt = 0; nt < 4; nt++) {
                cmax[nt][0] = fmaxf(cmax[nt][0], fmaxf(acc[nt][0], acc[nt][2]));
                cmax[nt][1] = fmaxf(cmax[nt][1], fmaxf(acc[nt][1], acc[nt][3]));
            }
        }

        // ---- epilogue: finish max over t (lanes t/4 groups), then sum over l ----
        float s = 0.0f;
        #pragma unroll
        for (int nt = 0; nt < 4; nt++) {
            #pragma unroll
            for (int j = 0; j < 2; j++) {
                float v = cmax[nt][j];
                v = fmaxf(v, __shfl_xor_sync(0xffffffffu, v, 4));
                v = fmaxf(v, __shfl_xor_sync(0xffffffffu, v, 8));
                v = fmaxf(v, __shfl_xor_sync(0xffffffffu, v, 16));
                s += v;
            }
        }
        // sum over the 4 n-lane groups (lane%4) -> total over all 32 l
        s += __shfl_xor_sync(0xffffffffu, s, 1);
        s += __shfl_xor_sync(0xffffffffu, s, 2);
        if (lane == 0) out[q * ND_ + d] = s;

        d = nd;
        if (it < ndocs - 1)
            __syncthreads();   // compute done before next prefetch overwrites a buffer
    }
}

// ---------------- launch ----------------

extern "C" void kernel_launch(void* const* d_in, const int* in_sizes, int n_in,
                              void* d_out, int out_size) {
    (void)in_sizes; (void)n_in; (void)out_size;
    const float* doc   = (const float*)d_in[0];   // [128,128,128] fp32
    const float* query = (const float*)d_in[1];   // [128,128,32]  fp32
    float* out = (float*)d_out;                   // [128,128]     fp32

    cvt_fused_kernel<<<CVT_DOC_BLOCKS + 128, 256>>>(doc, query);

    cudaFuncSetAttribute(colbert_maxsim_kernel,
                         cudaFuncAttributeMaxDynamicSharedMemorySize, SMEM_TOTAL);
    colbert_maxsim_kernel<<<dim3(16, DG_STRIDE, 1), 256, SMEM_TOTAL>>>(out);
}

// round 14
// speedup vs baseline: 1.0539x; 1.0539x over previous
#include <cuda_runtime.h>
#include <cuda_bf16.h>
#include <cstdint>

// Problem dims
#define ND_  128   // docs
#define LD_  128   // doc tokens (t)  -> GEMM M
#define E_   128   // embed          -> GEMM K
#define NQ_  128   // queries
#define LQ_  32    // query tokens (l)-> GEMM N

#define QG_PER_CTA 8    // queries per CTA (one per warp)
#define D_PER_CTA  2    // docs per CTA

// padded smem rows: 128 bf16 + 8 pad = 272 bytes (conflict-free ldmatrix)
#define ROW_B   272
#define QT_B    (32 * ROW_B)      // 8704 B per query tile
#define DT_B    (128 * ROW_B)     // 34816 B per doc tile
#define SMEM_TOTAL (2 * DT_B)     // 69632 B; query staging (8*QT_B) aliases this space

// bf16 scratch (module-scope device globals: no runtime allocation)
static __device__ __nv_bfloat16 g_doc[ND_ * LD_ * E_];   // [d][t][e]
static __device__ __nv_bfloat16 g_qT [NQ_ * LQ_ * E_];   // [q][l][e]

// ---------------- fused convert kernel ----------------
#define CVT_DOC_BLOCKS 512

__global__ void __launch_bounds__(256)
cvt_fused_kernel(const float* __restrict__ doc, const float* __restrict__ query) {
    __shared__ float s[128 * 33];   // query branch only
    if (blockIdx.x < CVT_DOC_BLOCKS) {
        int b0 = blockIdx.x * 1024 + threadIdx.x;
        float4 v[4];
        #pragma unroll
        for (int u = 0; u < 4; u++)
            v[u] = reinterpret_cast<const float4*>(doc)[b0 + u * 256];
        #pragma unroll
        for (int u = 0; u < 4; u++) {
            __nv_bfloat162 lo = __floats2bfloat162_rn(v[u].x, v[u].y);
            __nv_bfloat162 hi = __floats2bfloat162_rn(v[u].z, v[u].w);
            uint2 pk;
            pk.x = *reinterpret_cast<uint32_t*>(&lo);
            pk.y = *reinterpret_cast<uint32_t*>(&hi);
            reinterpret_cast<uint2*>(g_doc)[b0 + u * 256] = pk;
        }
    } else {
        int q   = blockIdx.x - CVT_DOC_BLOCKS;   // 0..127
        int tid = threadIdx.x;
        const float* p = query + q * 4096;
        #pragma unroll
        for (int j = 0; j < 16; j++) {
            int idx = tid + j * 256;               // idx = e*32 + l
            s[(idx >> 5) * 33 + (idx & 31)] = p[idx];
        }
        __syncthreads();
        #pragma unroll
        for (int j = 0; j < 16; j++) {
            int idx = tid + j * 256;               // idx = l*128 + e
            int l = idx >> 7, e = idx & 127;
            g_qT[q * 4096 + idx] = __float2bfloat16(s[e * 33 + l]);
        }
    }
}

// ---------------- PTX helpers ----------------

__device__ __forceinline__ uint32_t s2u(const void* p) {
    uint32_t a;
    asm("{ .reg .u64 t; cvta.to.shared.u64 t, %1; cvt.u32.u64 %0, t; }"
        : "=r"(a) : "l"(p));
    return a;
}

__device__ __forceinline__ void ldsm_x4(uint32_t& r0, uint32_t& r1,
                                        uint32_t& r2, uint32_t& r3, uint32_t addr) {
    asm volatile("ldmatrix.sync.aligned.m8n8.x4.shared.b16 {%0,%1,%2,%3}, [%4];"
                 : "=r"(r0), "=r"(r1), "=r"(r2), "=r"(r3) : "r"(addr));
}

__device__ __forceinline__ void mma16816(float* c, uint32_t a0, uint32_t a1,
                                         uint32_t a2, uint32_t a3,
                                         uint32_t b0, uint32_t b1) {
    asm volatile(
        "mma.sync.aligned.m16n8k16.row.col.f32.bf16.bf16.f32 "
        "{%0,%1,%2,%3}, {%4,%5,%6,%7}, {%8,%9}, {%0,%1,%2,%3};"
        : "+f"(c[0]), "+f"(c[1]), "+f"(c[2]), "+f"(c[3])
        : "r"(a0), "r"(a1), "r"(a2), "r"(a3), "r"(b0), "r"(b1));
}

__device__ __forceinline__ void cp_async16(uint32_t saddr, const void* gaddr) {
    asm volatile("cp.async.cg.shared.global [%0], [%1], 16;"
                 :: "r"(saddr), "l"(gaddr) : "memory");
}
__device__ __forceinline__ void cp_commit() {
    asm volatile("cp.async.commit_group;" ::: "memory");
}

// ---------------- main kernel ----------------
// grid (16 qgroups, 64 dgroups), 256 threads, 2 CTAs/SM.
// Warp w owns query w of the group (all 32 l-columns).
// Both doc tiles prefetched up front; 2 barriers total in the doc loop.

__global__ void __launch_bounds__(256, 2)
colbert_maxsim_kernel(float* __restrict__ out) {
    extern __shared__ char smem[];
    const uint32_t sb   = s2u(smem);
    const int tid  = threadIdx.x;
    const int wid  = tid >> 5;
    const int lane = tid & 31;
    const int qg   = blockIdx.x;   // 0..15
    const int dgp  = blockIdx.y;   // 0..63
    const int mi   = lane >> 3;    // ldmatrix 8-lane group 0..3

    // ---- 1) stage 8 query tiles into smem (region later reused as doc buffers) ----
    {
        const __nv_bfloat16* Q = g_qT + (size_t)qg * (QG_PER_CTA * LQ_ * E_);
        #pragma unroll
        for (int j = 0; j < 16; j++) {
            int c    = tid + j * 256;          // 4096 uint4 chunks total
            int tile = c >> 9;                 // 512 chunks per tile
            int rc   = c & 511;
            int row  = rc >> 4;                // 16 chunks per 128-bf16 row
            int col  = rc & 15;
            uint4 v = reinterpret_cast<const uint4*>(Q + tile * 4096 + row * 128)[col];
            *reinterpret_cast<uint4*>(smem + tile * QT_B + row * ROW_B + col * 16) = v;
        }
    }
    __syncthreads();

    // ---- 2) load this warp's entire B tile (32 l x 128 e) into 64 registers ----
    uint32_t breg[8][4][2];
    {
        const uint32_t qb = sb + wid * QT_B;
        #pragma unroll
        for (int k = 0; k < 8; k++) {
            #pragma unroll
            for (int p = 0; p < 2; p++) {
                uint32_t addr = qb + (uint32_t)((p * 16 + (mi >> 1) * 8 + (lane & 7)) * ROW_B
                                                + (k * 16 + (mi & 1) * 8) * 2);
                ldsm_x4(breg[k][2 * p][0], breg[k][2 * p][1],
                        breg[k][2 * p + 1][0], breg[k][2 * p + 1][1], addr);
            }
        }
    }
    __syncthreads();   // all warps done reading query smem; region is now free

    // ---- 3) prefetch BOTH doc tiles (separate commit groups) ----
    const uint32_t dbuf[2] = { sb, sb + DT_B };
    const int d0 = dgp * D_PER_CTA;

    #pragma unroll
    for (int it = 0; it < 2; it++) {
        const __nv_bfloat16* A = g_doc + (size_t)(d0 + it) * (LD_ * E_);
        #pragma unroll
        for (int j = 0; j < 8; j++) {
            int c = tid + j * 256;             // 2048 chunks
            int row = c >> 4, col = c & 15;
            cp_async16(dbuf[it] + row * ROW_B + col * 16, A + row * 128 + col * 8);
        }
        cp_commit();
    }

    // per-lane constant part of the A ldmatrix address
    const uint32_t a_lane_off = (uint32_t)(((mi & 1) * 8 + (lane & 7)) * ROW_B
                                           + ((mi >> 1) * 8) * 2);
    const int q = qg * QG_PER_CTA + wid;

    #pragma unroll 1
    for (int it = 0; it < D_PER_CTA; it++) {
        if (it == 0) { asm volatile("cp.async.wait_group 1;" ::: "memory"); }
        else         { asm volatile("cp.async.wait_group 0;" ::: "memory"); }
        __syncthreads();   // cross-thread visibility of this doc's tile

        const uint32_t ab = dbuf[it] + a_lane_off;

        float cmax[4][2];
        #pragma unroll
        for (int nt = 0; nt < 4; nt++) { cmax[nt][0] = -1e30f; cmax[nt][1] = -1e30f; }

        // ---- software-pipelined mainloop: flat j = mt*8+k, A-frag ping-pong,
        //      prefetch distance 2 (issued after the consuming MMA) ----
        uint32_t fa[2][4];
        ldsm_x4(fa[0][0], fa[0][1], fa[0][2], fa[0][3], ab);
        ldsm_x4(fa[1][0], fa[1][1], fa[1][2], fa[1][3], ab + 32);

        #pragma unroll 1
        for (int mt = 0; mt < 8; mt++) {
            const uint32_t bmt = ab + (uint32_t)(mt * 16 * ROW_B);

            float acc[4][4];
            #pragma unroll
            for (int nt = 0; nt < 4; nt++)
                #pragma unroll
                for (int r = 0; r < 4; r++) acc[nt][r] = 0.0f;

            #pragma unroll
            for (int k = 0; k < 8; k++) {
                // MMAs consume fa[k&1]
                #pragma unroll
                for (int nt = 0; nt < 4; nt++)
                    mma16816(acc[nt], fa[k & 1][0], fa[k & 1][1],
                             fa[k & 1][2], fa[k & 1][3],
                             breg[k][nt][0], breg[k][nt][1]);
                // prefetch j+2 into the slot just consumed (safe: operands read at issue)
                if (!(mt == 7 && k >= 6)) {
                    uint32_t pa = (k + 2 < 8)
                        ? (bmt + (uint32_t)((k + 2) * 32))
                        : (bmt + (uint32_t)(16 * ROW_B + (k - 6) * 32));
                    ldsm_x4(fa[k & 1][0], fa[k & 1][1],
                            fa[k & 1][2], fa[k & 1][3], pa);
                }
            }
            // running column-max over t (rows m and m+8 of this M-tile)
            #pragma unroll
            for (int nt = 0; nt < 4; nt++) {
                cmax[nt][0] = fmaxf(cmax[nt][0], fmaxf(acc[nt][0], acc[nt][2]));
                cmax[nt][1] = fmaxf(cmax[nt][1], fmaxf(acc[nt][1], acc[nt][3]));
            }
        }

        // ---- epilogue: finish max over t (lane row-groups), then sum over l ----
        float s = 0.0f;
        #pragma unroll
        for (int nt = 0; nt < 4; nt++) {
            #pragma unroll
            for (int j = 0; j < 2; j++) {
                float v = cmax[nt][j];
                v = fmaxf(v, __shfl_xor_sync(0xffffffffu, v, 4));
                v = fmaxf(v, __shfl_xor_sync(0xffffffffu, v, 8));
                v = fmaxf(v, __shfl_xor_sync(0xffffffffu, v, 16));
                s += v;
            }
        }
        // sum over the 4 n-lane groups (lane%4) -> total over all 32 l
        s += __shfl_xor_sync(0xffffffffu, s, 1);
        s += __shfl_xor_sync(0xffffffffu, s, 2);
        if (lane == 0) out[q * ND_ + (d0 + it)] = s;
        // no trailing barrier: doc1's buffer was loaded before doc0's compute
    }
}

// ---------------- launch ----------------

extern "C" void kernel_launch(void* const* d_in, const int* in_sizes, int n_in,
                              void* d_out, int out_size) {
    (void)in_sizes; (void)n_in; (void)out_size;
    const float* doc   = (const float*)d_in[0];   // [128,128,128] fp32
    const float* query = (const float*)d_in[1];   // [128,128,32]  fp32
    float* out = (float*)d_out;                   // [128,128]     fp32

    cvt_fused_kernel<<<CVT_DOC_BLOCKS + 128, 256>>>(doc, query);

    cudaFuncSetAttribute(colbert_maxsim_kernel,
                         cudaFuncAttributeMaxDynamicSharedMemorySize, SMEM_TOTAL);
    colbert_maxsim_kernel<<<dim3(16, 64, 1), 256, SMEM_TOTAL>>>(out);
}